// round 15
// baseline (speedup 1.0000x reference)
#include <cuda_runtime.h>

// 2-layer LSTM (B=2048, T=1000, I=13, H=32) + Linear(32)->ReLU->Linear(3).
// 148 blocks x 256 threads. Block = two independent 7-batch halves.
// Half = L0 group (64 thr) + L1 group (64 thr), pipelined one step apart over
// double-buffered h0 with parity-split barriers (R10 topology).
// NEW vs R10: thread (u, kh) owns ALL FOUR gate rows of unit u (i,f,g,o) for
// k-half kh, with kh mapped INSIDE the warp (lanes 0-15 kh0, 16-31 kh1):
//  - activation LDS per thread halves (42 vs 84) for the same 336 FFMA2;
//  - gate k-partials combine via __shfl_xor(16) — the gate smem roundtrip
//    and one GBAR per step are gone;
//  - EW operates on register-resident gates (kh0 lanes: batches 0-3,
//    kh1 lanes: batches 4-6) — no cross-thread gate reads at all.

#define BB    2048
#define TT    1000
#define II    13
#define HH    32
#define NC    3
#define NBH   7            // batches per half
#define BPB   14
#define GRIDN 148
#define GSTR  9

typedef unsigned long long ull;

struct alignas(16) Smem {
    float xs[2][2][NBH][16];   // [half][parity][b][k], k padded 13->16
    float h0[2][2][NBH][HH];   // [half][slot][b][k]
    float h1[2][NBH][HH];      // [half][b][k]
    float hs[2][HH * GSTR];    // classifier scratch
};

__device__ __forceinline__ ull ffma2(ull a, ull b, ull c) {
    ull d;
    asm("fma.rn.f32x2 %0, %1, %2, %3;" : "=l"(d) : "l"(a), "l"(b), "l"(c));
    return d;
}
__device__ __forceinline__ ull packf2(float lo, float hi) {
    ull r;
    asm("mov.b64 %0, {%1, %2};" : "=l"(r) : "f"(lo), "f"(hi));
    return r;
}
__device__ __forceinline__ float hadd2(ull a) {
    float lo, hi;
    asm("mov.b64 {%0, %1}, %2;" : "=f"(lo), "=f"(hi) : "l"(a));
    return lo + hi;
}
__device__ __forceinline__ ull d2l(double d) { return __double_as_longlong(d); }

__device__ __forceinline__ float tanhap(float v) {
    float y;
    asm("tanh.approx.f32 %0, %1;" : "=f"(y) : "f"(v));
    return y;
}
__device__ __forceinline__ float sigf(float v) {
    return fmaf(tanhap(0.5f * v), 0.5f, 0.5f);
}

// acc[q][b] += v-pairs * w[q]-pairs over NC4 float4 chunks of vb.
template <int NC4, int BSTR, int NW>
__device__ __forceinline__ void gemm4(ull (&acc)[4][NBH], const float* __restrict__ vb,
                                      const ull (&w)[4][NW]) {
#pragma unroll
    for (int c = 0; c < NC4; c++) {
#pragma unroll
        for (int b = 0; b < NBH; b++) {
            double2 v = *reinterpret_cast<const double2*>(vb + b * BSTR + c * 4);
            ull vx = d2l(v.x), vy = d2l(v.y);
#pragma unroll
            for (int q = 0; q < 4; q++) {
                acc[q][b] = ffma2(vx, w[q][2 * c],     acc[q][b]);
                acc[q][b] = ffma2(vy, w[q][2 * c + 1], acc[q][b]);
            }
        }
    }
}

__global__ void __launch_bounds__(256, 1)
lstm_fused_kernel(const float* __restrict__ x,
                  const float* __restrict__ Wih0, const float* __restrict__ Whh0,
                  const float* __restrict__ bih0, const float* __restrict__ bhh0,
                  const float* __restrict__ Wih1, const float* __restrict__ Whh1,
                  const float* __restrict__ bih1, const float* __restrict__ bhh1,
                  const float* __restrict__ Wc1,  const float* __restrict__ bc1,
                  const float* __restrict__ Wc2,  const float* __restrict__ bc2,
                  float* __restrict__ out) {
    __shared__ Smem s;
    const int tid  = threadIdx.x;
    const int half = tid >> 7;
    const int lt   = tid & 127;
    const int grp  = lt >> 6;
    const int gl   = lt & 63;            // thread within group
    const int wg   = gl >> 5;            // warp within group
    const int lane = gl & 31;
    const int kh   = lane >> 4;          // k-half (inside warp!)
    const int u    = wg * 16 + (lane & 15);   // owned unit
    const bool is_l0 = ((grp ^ half) == 0);   // SMSP-balanced layer map
    const int bbase = blockIdx.x * BPB + half * NBH;

    // ---- zero state (xs, h0, h1 contiguous at struct start) ----
    {
        float* zp = reinterpret_cast<float*>(&s);
        const int zn = (int)((sizeof(s.xs) + sizeof(s.h0) + sizeof(s.h1)) / 4);
        for (int i = tid; i < zn; i += 256) zp[i] = 0.0f;
    }
    // ---- stage x(0) (batch-clamped for tail blocks) ----
    for (int i = tid; i < 2 * NBH * II; i += 256) {
        int hf = i / (NBH * II), r = i % (NBH * II), b = r / II, k = r % II;
        int gb = blockIdx.x * BPB + hf * NBH + b;
        if (gb > BB - 1) gb = BB - 1;
        s.xs[hf][0][b][k] = x[(size_t)gb * TT * II + k];
    }

    // ---- register-resident weights: 4 rows (u+32q), k-half kh ----
    // L0: wX[4][4] (Wih0 slice), wH[4][8] (Whh0 slice)
    // L1: wX[4][8] (Wih1 slice), wH[4][8] (Whh1 slice)
    ull wX0[4][4], wXH[4][8], wH[4][8];
    ull bias[4];
    if (is_l0) {
#pragma unroll
        for (int q = 0; q < 4; q++) {
            int r = u + 32 * q;
#pragma unroll
            for (int p = 0; p < 4; p++) {
                int k = (kh * 4 + p) * 2;
                float lo = (k     < II) ? Wih0[r * II + k]     : 0.0f;
                float hi = (k + 1 < II) ? Wih0[r * II + k + 1] : 0.0f;
                wX0[q][p] = packf2(lo, hi);
            }
#pragma unroll
            for (int p = 0; p < 8; p++) {
                int k = (kh * 8 + p) * 2;
                wH[q][p] = packf2(Whh0[r * HH + k], Whh0[r * HH + k + 1]);
            }
            bias[q] = (kh == 0) ? packf2(bih0[r] + bhh0[r], 0.0f) : 0ull;
        }
    } else {
#pragma unroll
        for (int q = 0; q < 4; q++) {
            int r = u + 32 * q;
#pragma unroll
            for (int p = 0; p < 8; p++) {
                int k = (kh * 8 + p) * 2;
                wXH[q][p] = packf2(Wih1[r * HH + k], Wih1[r * HH + k + 1]);
                wH[q][p]  = packf2(Whh1[r * HH + k], Whh1[r * HH + k + 1]);
            }
            bias[q] = (kh == 0) ? packf2(bih1[r] + bhh1[r], 0.0f) : 0ull;
        }
    }

    float cst[4] = {0.f, 0.f, 0.f, 0.f};

    // ---- x staging slots (L0 threads): slots gl and gl+64 ----
    const int pb0 = gl >> 4,        pk0 = gl & 15;
    const int pb1 = (gl + 64) >> 4, pk1 = (gl + 64) & 15;
    const bool pv0 = (pb0 < NBH) && (pk0 < II);
    const bool pv1 = (pb1 < NBH) && (pk1 < II);
    int cb0 = bbase + pb0; if (cb0 > BB - 1) cb0 = BB - 1;
    int cb1 = bbase + pb1; if (cb1 > BB - 1) cb1 = BB - 1;
    const float* xc0 = x + (size_t)cb0 * TT * II + pk0;
    const float* xc1 = x + (size_t)cb1 * TT * II + pk1;

    // barrier ids: idA[slot]=1+4h+slot, idB[slot]=3+4h+slot, GBAR=9+2h+grp
    const int idA0 = 1 + 4 * half;
    const int idB0 = 3 + 4 * half;
    const int idG  = 9 + 2 * half + grp;

    __syncthreads();

#define ARRV(id) asm volatile("bar.arrive %0, 128;" :: "r"(id) : "memory")
#define WAIT(id) asm volatile("bar.sync %0, 128;"   :: "r"(id) : "memory")
#define GBAR()   asm volatile("bar.sync %0, 64;"    :: "r"(idG) : "memory")

    for (int t = 0; t <= TT; t++) {
        const int par = t & 1;
        if (is_l0) {
            if (t < TT) {
                GBAR();   // intra-L0: h0(t-1) slot par / xs(t) visible
                float xn0 = 0.f, xn1 = 0.f;
                if (t + 1 < TT) {
                    if (pv0) xn0 = xc0[(size_t)(t + 1) * II];
                    if (pv1) xn1 = xc1[(size_t)(t + 1) * II];
                }
                // GEMM0 (k-slice): b0 + Wx0*x(t) + Wh0*h0(t-1)
                const float* xsv = &s.xs[half][par][0][0] + kh * 8;
                const float* h0v = &s.h0[half][par][0][0] + kh * 16;
                ull acc[4][NBH];
#pragma unroll
                for (int b = 0; b < NBH; b++)
#pragma unroll
                    for (int q = 0; q < 4; q++) acc[q][b] = bias[q];
                gemm4<2, 16, 4>(acc, xsv, wX0);
                gemm4<4, HH, 8>(acc, h0v, wH);
                if (t >= 2) WAIT(idB0 + (par ^ 1));  // L1 done with slot par^1
                // combine k-halves via shuffle; EW on owned batches
#pragma unroll
                for (int b = 0; b < NBH; b++) {
                    float gi = hadd2(acc[0][b]); gi += __shfl_xor_sync(~0u, gi, 16);
                    float gf = hadd2(acc[1][b]); gf += __shfl_xor_sync(~0u, gf, 16);
                    float gg = hadd2(acc[2][b]); gg += __shfl_xor_sync(~0u, gg, 16);
                    float go = hadd2(acc[3][b]); go += __shfl_xor_sync(~0u, go, 16);
                    if ((b < 4) == (kh == 0)) {
                        int ci = (kh == 0) ? b : b - 4;
                        float ig = sigf(gi), fg = sigf(gf);
                        float gv = tanhap(gg), og = sigf(go);
                        cst[ci] = fmaf(fg, cst[ci], ig * gv);
                        s.h0[half][par ^ 1][b][u] = og * tanhap(cst[ci]);
                    }
                }
                ARRV(idA0 + (par ^ 1));              // h0(t) published
                if (t + 1 < TT) {
                    if (pv0) s.xs[half][par ^ 1][pb0][pk0] = xn0;
                    if (pv1) s.xs[half][par ^ 1][pb1][pk1] = xn1;
                }
            }
        } else {
            if (t > 0) {
                // private part first: b1 + Whh1*h1(t-2) (k-slice)
                const float* h1v = &s.h1[half][0][0] + kh * 16;
                ull acc[4][NBH];
#pragma unroll
                for (int b = 0; b < NBH; b++)
#pragma unroll
                    for (int q = 0; q < 4; q++) acc[q][b] = bias[q];
                gemm4<4, HH, 8>(acc, h1v, wH);
                WAIT(idA0 + par);                    // h0(t-1) ready in slot par
                const float* h0v = &s.h0[half][par][0][0] + kh * 16;
                gemm4<4, HH, 8>(acc, h0v, wXH);
                ARRV(idB0 + par);                    // slot par consumed
                // combine + EW -> h1(t-1)
#pragma unroll
                for (int b = 0; b < NBH; b++) {
                    float gi = hadd2(acc[0][b]); gi += __shfl_xor_sync(~0u, gi, 16);
                    float gf = hadd2(acc[1][b]); gf += __shfl_xor_sync(~0u, gf, 16);
                    float gg = hadd2(acc[2][b]); gg += __shfl_xor_sync(~0u, gg, 16);
                    float go = hadd2(acc[3][b]); go += __shfl_xor_sync(~0u, go, 16);
                    if ((b < 4) == (kh == 0)) {
                        int ci = (kh == 0) ? b : b - 4;
                        float ig = sigf(gi), fg = sigf(gf);
                        float gv = tanhap(gg), og = sigf(go);
                        cst[ci] = fmaf(fg, cst[ci], ig * gv);
                        s.h1[half][b][u] = og * tanhap(cst[ci]);
                    }
                }
                GBAR();                              // h1 visible in-group
            }
        }
    }
    __syncthreads();

    // ---- classifier head ----
    {
        int hj = lt & 31, hb = lt >> 5;
        float* hs = s.hs[half];
#pragma unroll
        for (int s2 = 0; s2 < 2; s2++) {
            int b = hb + 4 * s2;
            if (b < NBH) {
                float a = bc1[hj];
#pragma unroll
                for (int k = 0; k < HH; k++)
                    a = fmaf(s.h1[half][b][k], Wc1[hj * HH + k], a);
                hs[hj * GSTR + b] = fmaxf(a, 0.0f);
            }
        }
    }
    __syncthreads();
    if (lt < NBH * NC) {
        int b = lt / NC, c = lt - b * NC;
        if (bbase + b < BB) {
            float* hs = s.hs[half];
            float o = bc2[c];
#pragma unroll
            for (int j = 0; j < HH; j++)
                o = fmaf(hs[j * GSTR + b], Wc2[c * HH + j], o);
            out[(size_t)(bbase + b) * NC + c] = o;
        }
    }
#undef ARRV
#undef WAIT
#undef GBAR
}

extern "C" void kernel_launch(void* const* d_in, const int* in_sizes, int n_in,
                              void* d_out, int out_size) {
    const float* x    = (const float*)d_in[0];
    const float* Wih0 = (const float*)d_in[1];
    const float* Whh0 = (const float*)d_in[2];
    const float* bih0 = (const float*)d_in[3];
    const float* bhh0 = (const float*)d_in[4];
    const float* Wih1 = (const float*)d_in[5];
    const float* Whh1 = (const float*)d_in[6];
    const float* bih1 = (const float*)d_in[7];
    const float* bhh1 = (const float*)d_in[8];
    const float* Wc1  = (const float*)d_in[9];
    const float* bc1  = (const float*)d_in[10];
    const float* Wc2  = (const float*)d_in[11];
    const float* bc2  = (const float*)d_in[12];
    float* out = (float*)d_out;

    lstm_fused_kernel<<<GRIDN, 256>>>(
        x, Wih0, Whh0, bih0, bhh0, Wih1, Whh1, bih1, bhh1,
        Wc1, bc1, Wc2, bc2, out);
}